// round 17
// baseline (speedup 1.0000x reference)
#include <cuda_runtime.h>

typedef unsigned long long u64;

#define NBINS  4
#define NFEAT  48
#define KTOT   2048
#define NT     16            // batch rows per unit
#define TLEN   154
#define OUTF   (NBINS * NFEAT)
#define NCTAS  148
#define CHUNKK 256           // pooled k per chunk
#define SLOTF  (CHUNKK * 16) // data floats per slot: 4096 (16KB)
#define NSLOTS 4
#define CPU    8             // chunks per unit
#define NTHREADS 768         // 16 consumer warps + 8 producer warps

#define WPWC   (3 * CHUNKK)            // weight floats per warp per chunk: 768
#define WBUF   (16 * WPWC)             // per chunk-buffer: 12288 floats (48KB)
#define WOFF   (NSLOTS * SLOTF)        // weights start: 16384 floats
#define TOTSMF (WOFF + 3 * WBUF)       // 53248 floats = 208KB

// named barrier ids: full[s] = s (0..3), empty[s] = 4+s (4..7)
#define BAR_SYNC(id)   asm volatile("bar.sync %0, %1;"   :: "r"(id), "r"(NTHREADS) : "memory")
#define BAR_ARRIVE(id) asm volatile("bar.arrive %0, %1;" :: "r"(id), "r"(NTHREADS) : "memory")

__device__ float g_Weff[NBINS * NFEAT * KTOT];  // [bf][k]

__constant__ float c_dec_lo[8] = {
    -0.010597401784997278f,  0.032883011666982945f,  0.030841381835986965f,
    -0.18703481171888114f,  -0.02798376941698385f,   0.6308807679295904f,
     0.7148465705525415f,    0.23037781330885523f };
__constant__ float c_dec_hi[8] = {
    -0.23037781330885523f,   0.7148465705525415f,   -0.6308807679295904f,
    -0.02798376941698385f,   0.18703481171888114f,   0.030841381835986965f,
    -0.032883011666982945f, -0.010597401784997278f };

__device__ __forceinline__ u64 ffma2(u64 a, u64 b, u64 c) {
    u64 d; asm("fma.rn.f32x2 %0, %1, %2, %3;" : "=l"(d) : "l"(a), "l"(b), "l"(c));
    return d;
}
__device__ __forceinline__ u64 fadd2(u64 a, u64 b) {
    u64 d; asm("add.rn.f32x2 %0, %1, %2;" : "=l"(d) : "l"(a), "l"(b));
    return d;
}
__device__ __forceinline__ u64 dup2(float x) {
    u64 d; asm("mov.b64 %0, {%1, %1};" : "=l"(d) : "f"(x));
    return d;
}
__device__ __forceinline__ float2 unpack2(u64 a) {
    float2 v; asm("mov.b64 {%0, %1}, %2;" : "=f"(v.x), "=f"(v.y) : "l"(a));
    return v;
}

// ============================================================
// Adjoint of one analysis level (R16, proven).
// ============================================================
__device__ __forceinline__ float adj_level(const float* __restrict__ lo,
                                           const float* __restrict__ hi,
                                           int N, int out, int j, int hw)
{
    float acc = 0.0f;
    #pragma unroll
    for (int u = 0; u < 8; ++u) {
        const float f0 = c_dec_lo[7 - u];
        const float f1 = c_dec_hi[7 - u];
        int num = j + 6 - u;
        if (num >= 0 && (num & 1) == 0) {
            int i = num >> 1;
            if (i < out) acc += f0 * lo[i * 16 + hw] + f1 * hi[i * 16 + hw];
        }
        if (j > 0 && j <= 6) {
            int num2 = -j + 6 - u;
            if (num2 >= 0 && (num2 & 1) == 0) {
                int i = num2 >> 1;
                if (i < out) acc += f0 * lo[i * 16 + hw] + f1 * hi[i * 16 + hw];
            }
        }
        int rr = 2 * N - 2 - j;
        if (rr >= N) {
            int num3 = rr + 6 - u;
            if ((num3 & 1) == 0) {
                int i = num3 >> 1;
                if (i >= 0 && i < out)
                    acc += f0 * lo[i * 16 + hw] + f1 * hi[i * 16 + hw];
            }
        }
    }
    return acc;
}

// ============================================================
// Weight builder via adjoint DWT (R16, proven; ~3us).
// ============================================================
__global__ void fold_adjoint(const float* __restrict__ conv_w) {
    __shared__ float Ws[TLEN * 16];
    __shared__ float y22[22 * 16];
    __shared__ float y37[37 * 16];
    __shared__ float y67[67 * 16];
    const int bf = blockIdx.x;
    const int tid = threadIdx.x;

    for (int i = tid; i < TLEN * 16; i += 256)
        Ws[i] = conv_w[(size_t)bf * (TLEN * 16) + i];
    __syncthreads();

    for (int idx = tid; idx < 22 * 16; idx += 256) {
        int j = idx >> 4, hw = idx & 15;
        y22[idx] = adj_level(Ws, Ws + 140 * 16, 22, 14, j, hw);
    }
    __syncthreads();
    for (int idx = tid; idx < 37 * 16; idx += 256) {
        int j = idx >> 4, hw = idx & 15;
        y37[idx] = adj_level(y22, Ws + 118 * 16, 37, 22, j, hw);
    }
    __syncthreads();
    for (int idx = tid; idx < 67 * 16; idx += 256) {
        int j = idx >> 4, hw = idx & 15;
        y67[idx] = adj_level(y37, Ws + 81 * 16, 67, 37, j, hw);
    }
    __syncthreads();
    for (int idx = tid; idx < 128 * 16; idx += 256) {
        int j = idx >> 4, hw = idx & 15;
        g_Weff[(size_t)bf * KTOT + idx] =
            adj_level(y67, Ws + 14 * 16, 128, 67, j, hw);
    }
}

// ============================================================
// Producer pieces (R10, proven). Chunk = 256 pooled k x 16 n.
// Per thread ONE float4 per n-row -> 16 LDG.128 per chunk,
// front-batched (loadchunk), consumed a full ring cycle later
// (poolstore). Slot layout: buf[np*512 + 2*k + hal], k0 even.
// ============================================================
__device__ __forceinline__ void loadchunk(const float* __restrict__ x,
                                          int b, int g, int ci, int ntot,
                                          int ptid, float4* v0, float4* v1)
{
    const int n0 = g * NT;
    #pragma unroll
    for (int np = 0; np < 8; ++np) {
        int ne = n0 + 2 * np;
        int no = ne + 1;
        if (ne >= ntot) ne = ntot - 1;
        if (no >= ntot) no = ntot - 1;
        const float4* xg0 = reinterpret_cast<const float4*>(
            x + ((size_t)ne * 512 + b * 128 + ci * 16) * 64);
        const float4* xg1 = reinterpret_cast<const float4*>(
            x + ((size_t)no * 512 + b * 128 + ci * 16) * 64);
        v0[np] = xg0[ptid];
        v1[np] = xg1[ptid];
    }
}

__device__ __forceinline__ void poolstore(float* __restrict__ buf, int ptid,
                                          const float4* v0, const float4* v1)
{
    const int tl = ptid >> 4;
    const int h  = (ptid >> 2) & 3;
    const int qh = ptid & 1;
    const int k0 = tl * 16 + h * 4 + 2 * qh;   // even, 0..254
    const bool owner = ((ptid & 2) == 0);
    #pragma unroll
    for (int np = 0; np < 8; ++np) {
        float a0 = fmaxf(v0[np].x, v0[np].y), c0 = fmaxf(v0[np].z, v0[np].w);
        float a1 = fmaxf(v1[np].x, v1[np].y), c1 = fmaxf(v1[np].z, v1[np].w);
        a0 = fmaxf(a0, __shfl_xor_sync(0xffffffffu, a0, 2));
        c0 = fmaxf(c0, __shfl_xor_sync(0xffffffffu, c0, 2));
        a1 = fmaxf(a1, __shfl_xor_sync(0xffffffffu, a1, 2));
        c1 = fmaxf(c1, __shfl_xor_sync(0xffffffffu, c1, 2));
        if (owner) {
            *reinterpret_cast<float4*>(buf + np * 512 + 2 * k0) =
                make_float4(a0, a1, c0, c1);
        }
    }
}

// ============================================================
// Main: persistent, warp-specialized, 4-slot data ring +
// per-warp cp.async weight staging (3-deep, no barriers —
// each consumer warp reads ONLY its own 3 feature rows, so
// weight buffers are warp-private and ordered by program order
// + cp.async.wait_group). 148 CTAs x 768 threads, 208KB smem.
// ============================================================
__global__ __launch_bounds__(NTHREADS, 1)
void dwt_main_kernel(const float* __restrict__ x,
                     const float* __restrict__ conv_b,
                     float* __restrict__ out, int ntot, int groups)
{
    extern __shared__ float sm[];
    const int tid  = threadIdx.x;
    const int warp = tid >> 5;
    const int lane = tid & 31;
    const int cta  = blockIdx.x;
    const int G    = gridDim.x;
    const int nunits = NBINS * groups;
    const int myUnits = (cta < nunits) ? ((nunits - 1 - cta) / G + 1) : 0;
    const int totalChunks = CPU * myUnits;

    u64 acc[3][8];
    #pragma unroll
    for (int f = 0; f < 3; ++f)
        #pragma unroll
        for (int p = 0; p < 8; ++p) acc[f][p] = 0ull;

    if (warp < 16) {
        #pragma unroll
        for (int s = 0; s < NSLOTS; ++s) BAR_ARRIVE(4 + s);
    }

    if (warp >= 16) {
        // ========== producers (R10 pipelined, 4-slot ring) ==========
        const int ptid = tid - 512;
        float4 v0[8], v1[8];
        if (totalChunks > 0) {
            loadchunk(x, cta / groups, cta % groups, 0, ntot, ptid, v0, v1);
        }
        int slot = 0;
        for (int sc = 0; sc < totalChunks; ++sc) {
            BAR_SYNC(4 + slot);                 // wait empty
            poolstore(sm + slot * SLOTF, ptid, v0, v1);
            int s2 = sc + 1;
            if (s2 < totalChunks) {
                int u2 = cta + G * (s2 >> 3);
                loadchunk(x, u2 / groups, u2 % groups, s2 & 7, ntot,
                          ptid, v0, v1);
            }
            BAR_ARRIVE(slot);                   // mark full
            if (++slot == NSLOTS) slot = 0;
        }
    } else {
        // ================= consumers =================
        const unsigned sbase = (unsigned)__cvta_generic_to_shared(sm);
        const float4* wsrc = reinterpret_cast<const float4*>(g_Weff);

        // stage this warp's 3 feature rows for chunk sc2 (6 x 16B/thread)
        auto issue_w = [&](int sc2) {
            if (sc2 < totalChunks) {
                int u2 = cta + G * (sc2 >> 3);
                int b2 = u2 / groups;
                int ci2 = sc2 & 7;
                #pragma unroll
                for (int i = 0; i < 6; ++i) {
                    int jj = lane + 32 * i;         // 0..191
                    int f = jj >> 6, col = jj & 63;
                    unsigned dst = sbase +
                        ((WOFF + (sc2 % 3) * WBUF + warp * WPWC
                          + f * CHUNKK + col * 4) << 2);
                    const float4* src = wsrc
                        + (size_t)(b2 * NFEAT + warp * 3 + f) * (KTOT / 4)
                        + ci2 * (CHUNKK / 4) + col;
                    asm volatile("cp.async.cg.shared.global [%0], [%1], 16;"
                                 :: "r"(dst), "l"(src));
                }
            }
            asm volatile("cp.async.commit_group;");
        };

        issue_w(0);
        issue_w(1);

        int slot = 0;
        for (int sc = 0; sc < totalChunks; ++sc) {
            const int u  = cta + G * (sc >> 3);
            const int b  = u / groups;
            const int g  = u % groups;
            const int ci = sc & 7;
            float* buf = sm + slot * SLOTF;

            BAR_SYNC(slot);                     // wait data full
            asm volatile("cp.async.wait_group 1;");  // this chunk's weights

            const float* smk  = buf + 2 * lane;
            const float* wrow = sm + WOFF + (sc % 3) * WBUF + warp * WPWC + lane;

            float w0[3], w1[3];
            #pragma unroll
            for (int f = 0; f < 3; ++f) w0[f] = wrow[f * CHUNKK];
            #pragma unroll
            for (int f = 0; f < 3; ++f) w1[f] = wrow[f * CHUNKK + 32];

            #pragma unroll 1
            for (int jl = 0; jl < 8; jl += 2) {
                {   // even jl
                    u64 p2[8];
                    #pragma unroll
                    for (int pl = 0; pl < 8; ++pl)
                        p2[pl] = *reinterpret_cast<const u64*>(
                            smk + pl * 512 + 64 * jl);
                    float a0 = w0[0], a1 = w0[1], a2 = w0[2];
                    if (jl + 2 < 8) {
                        #pragma unroll
                        for (int f = 0; f < 3; ++f)
                            w0[f] = wrow[f * CHUNKK + 32 * (jl + 2)];
                    }
                    u64 d0 = dup2(a0), d1 = dup2(a1), d2 = dup2(a2);
                    #pragma unroll
                    for (int pl = 0; pl < 8; ++pl) {
                        acc[0][pl] = ffma2(d0, p2[pl], acc[0][pl]);
                        acc[1][pl] = ffma2(d1, p2[pl], acc[1][pl]);
                        acc[2][pl] = ffma2(d2, p2[pl], acc[2][pl]);
                    }
                }
                {   // odd jl
                    u64 p2[8];
                    #pragma unroll
                    for (int pl = 0; pl < 8; ++pl)
                        p2[pl] = *reinterpret_cast<const u64*>(
                            smk + pl * 512 + 64 * (jl + 1));
                    float a0 = w1[0], a1 = w1[1], a2 = w1[2];
                    if (jl + 3 < 8) {
                        #pragma unroll
                        for (int f = 0; f < 3; ++f)
                            w1[f] = wrow[f * CHUNKK + 32 * (jl + 3)];
                    }
                    u64 d0 = dup2(a0), d1 = dup2(a1), d2 = dup2(a2);
                    #pragma unroll
                    for (int pl = 0; pl < 8; ++pl) {
                        acc[0][pl] = ffma2(d0, p2[pl], acc[0][pl]);
                        acc[1][pl] = ffma2(d1, p2[pl], acc[1][pl]);
                        acc[2][pl] = ffma2(d2, p2[pl], acc[2][pl]);
                    }
                }
            }

            BAR_ARRIVE(4 + slot);               // mark data empty

            if (ci == CPU - 1) {
                // ---- epilogue: butterfly reduce + store + reset ----
                #pragma unroll
                for (int off = 16; off; off >>= 1)
                    #pragma unroll
                    for (int f = 0; f < 3; ++f)
                        #pragma unroll
                        for (int pl = 0; pl < 8; ++pl)
                            acc[f][pl] = fadd2(acc[f][pl],
                                __shfl_xor_sync(0xffffffffu, acc[f][pl], off));
                if (lane == 0) {
                    int n0 = g * NT;
                    #pragma unroll
                    for (int f = 0; f < 3; ++f) {
                        int fgl = warp * 3 + f;
                        float bias = conv_b[b * NFEAT + fgl];
                        #pragma unroll
                        for (int pl = 0; pl < 8; ++pl) {
                            float2 v = unpack2(acc[f][pl]);
                            int na = n0 + 2 * pl;
                            float ya = v.x + bias; ya = (ya > 0.0f) ? ya : 0.02f * ya;
                            float yb = v.y + bias; yb = (yb > 0.0f) ? yb : 0.02f * yb;
                            if (na < ntot)
                                out[(size_t)na * OUTF + b * NFEAT + fgl] = ya;
                            if (na + 1 < ntot)
                                out[(size_t)(na + 1) * OUTF + b * NFEAT + fgl] = yb;
                        }
                    }
                }
                #pragma unroll
                for (int f = 0; f < 3; ++f)
                    #pragma unroll
                    for (int pl = 0; pl < 8; ++pl) acc[f][pl] = 0ull;
            }

            issue_w(sc + 2);                    // stage next-next weights
            if (++slot == NSLOTS) slot = 0;
        }
    }
}

// ============================================================
extern "C" void kernel_launch(void* const* d_in, const int* in_sizes, int n_in,
                              void* d_out, int out_size)
{
    const float* x      = (const float*)d_in[0];  // (n,1,512,8,8)
    const float* conv_w = (const float*)d_in[1];  // (4,48,154,4,4)
    const float* conv_b = (const float*)d_in[2];  // (4,48)
    float* out = (float*)d_out;                   // (n,192)

    int ntot   = in_sizes[0] / (512 * 64);
    int groups = (ntot + NT - 1) / NT;

    fold_adjoint<<<NBINS * NFEAT, 256>>>(conv_w);

    cudaFuncSetAttribute(dwt_main_kernel,
                         cudaFuncAttributeMaxDynamicSharedMemorySize,
                         TOTSMF * 4);
    dwt_main_kernel<<<NCTAS, NTHREADS, TOTSMF * 4>>>(x, conv_b, out, ntot, groups);
}